// round 7
// baseline (speedup 1.0000x reference)
#include <cuda_runtime.h>
#include <cstdint>

// SKA: out[n, g*8+c, h, w] = sum_{7x7} x_pad[n, g*8+c, h+i, w+j] * w[n, c, i*7+j, h, w]
// x [8,512,96,96] f32, w [8,8,49,96,96] f32, out [8,512,96,96] f32.
//
// R7: same dataflow as the R6 winner (1 f32x2 output pair per thread, 49 weight
// pairs register-cached across all 64 g; even taps packed fma.rn.f32x2, odd taps
// scalar FMAs on free pair-splits; 4-buffer depth-3 cp.async pipeline). Change:
// CTA shrinks to 2 output rows / 96 threads with FOUR CTAs co-resident per SM
// (launch_bounds(96,4), 162*96*4 regs just fits the RF). Same 12 warps/SM, but
// 4 independent barrier domains -> a __syncthreads stalls 3 warps, not 6.
// Also fixes the tail wait_group (group `it` is now always provably complete).

#define N_    8
#define IC    512
#define H_    96
#define W_    96
#define WC    8
#define G_    64
#define KS    7
#define PAD   3
#define HT    2                     // output rows per CTA
#define PAIRS 48
#define NTHR  (PAIRS * HT)          // 96
#define TROWS (HT + 2 * PAD)        // 8 staged rows
#define PITCH 104                   // 3 zero | 96 data | 5 zero (floats)
#define TILE_F (TROWS * PITCH)      // 832 floats per channel slab
#define HW    (H_ * W_)             // 9216
#define CSTR  ((size_t)WC * HW)     // x/out channel stride between g steps
#define NIT   (G_ / 2)              // 32 pipeline stages (2 channels each)
#define ELPT  ((TROWS * W_) / NTHR) // 8 staged elements per thread per channel

typedef unsigned long long u64;

static __device__ __forceinline__ void ffma2(u64& d, u64 a, u64 b) {
    asm("fma.rn.f32x2 %0, %1, %2, %0;" : "+l"(d) : "l"(a), "l"(b));
}
// lo += xl*w.lo, hi += xh*w.hi; splitting the weight pair is register aliasing.
static __device__ __forceinline__ void odd_tap(float& lo, float& hi,
                                               float xl, float xh, u64 w) {
    asm("{\n\t"
        ".reg .f32 wl, wh;\n\t"
        "mov.b64 {wl, wh}, %4;\n\t"
        "fma.rn.f32 %0, %2, wl, %0;\n\t"
        "fma.rn.f32 %1, %3, wh, %1;\n\t"
        "}" : "+f"(lo), "+f"(hi) : "f"(xl), "f"(xh), "l"(w));
}
static __device__ __forceinline__ void unpack2(u64 v, float& a, float& b) {
    asm("mov.b64 {%0, %1}, %2;" : "=f"(a), "=f"(b) : "l"(v));
}
static __device__ __forceinline__ u64 pack2(float a, float b) {
    u64 r; asm("mov.b64 %0, {%1, %2};" : "=l"(r) : "f"(a), "f"(b)); return r;
}
static __device__ __forceinline__ void cp4(uint32_t s, const float* g, int sz) {
    asm volatile("cp.async.ca.shared.global [%0], [%1], 4, %2;"
                 :: "r"(s), "l"(g), "r"(sz));
}

__global__ __launch_bounds__(NTHR, 4)
void ska_kernel(const float* __restrict__ x, const float* __restrict__ wgt,
                float* __restrict__ out) {
    __shared__ float smem[8 * TILE_F];   // 4 buffers x 2 channel slabs = 26 KB

    const int tid = threadIdx.x;
    const int ht  = blockIdx.x;          // 0..47
    const int c   = blockIdx.y;          // 0..7
    const int n   = blockIdx.z;          // 0..7
    const int h0  = ht * HT;
    const int r   = tid / PAIRS;         // 0..1
    const int p   = tid % PAIRS;
    const int h   = h0 + r;
    const int w0  = 2 * p;

    // Zero left/right halo columns of all 8 slabs (written once, never again).
    for (int z = tid; z < 8 * TROWS * 8; z += NTHR) {
        int b = z / (TROWS * 8), rem = z % (TROWS * 8);
        int row = rem / 8, ci = rem % 8;
        int col = (ci < 3) ? ci : 99 + (ci - 3);
        smem[b * TILE_F + row * PITCH + col] = 0.0f;
    }

    // Register-cache this pixel-pair's 49 weight pairs (reused for all 64 g).
    const float* wb = wgt + ((size_t)(n * WC + c) * 49) * HW + (size_t)h * W_ + w0;
    u64 Wr[49];
    #pragma unroll
    for (int t = 0; t < 49; t++) Wr[t] = *(const u64*)(wb + (size_t)t * HW);

    const float* xc = x + (size_t)n * IC * HW + (size_t)c * HW;  // g=0 channel
    const uint32_t sbase = (uint32_t)__cvta_generic_to_shared(smem);

    // Hoisted staging descriptors: exactly ELPT=8 elements/thread/channel.
    uint32_t soff[ELPT];   // smem byte offset within a slab
    int      gofs[ELPT];   // float offset within a channel (row-clamped)
    int      gsz[ELPT];    // 4 = copy, 0 = zero-fill (OOB row)
    #pragma unroll
    for (int k = 0; k < ELPT; k++) {
        int idx = tid + k * NTHR;            // 0..767
        int row = idx / W_, col = idx - row * W_;
        int hr  = h0 - PAD + row;
        gsz[k]  = (hr >= 0 && hr < H_) ? 4 : 0;
        int hrc = hr < 0 ? 0 : (hr >= H_ ? H_ - 1 : hr);
        soff[k] = (uint32_t)(row * PITCH + 3 + col) * 4u;
        gofs[k] = hrc * W_ + col;
    }

    // Stage channels (2s, 2s+1) into buffer s%4; commit one cp.async group.
    auto stage = [&](int s) {
        #pragma unroll
        for (int cc = 0; cc < 2; cc++) {
            uint32_t sb = sbase + (uint32_t)(((s & 3) * 2 + cc) * TILE_F) * 4u;
            const float* base = xc + (size_t)(2 * s + cc) * CSTR;
            #pragma unroll
            for (int k = 0; k < ELPT; k++)
                cp4(sb + soff[k], base + gofs[k], gsz[k]);
        }
        asm volatile("cp.async.commit_group;");
    };

    stage(0);
    stage(1);
    stage(2);

    float* op = out + (size_t)n * IC * HW + (size_t)c * HW + (size_t)h * W_ + w0;

    for (int it = 0; it < NIT; ++it) {
        // Group `it` must be complete in THIS thread before the barrier makes
        // its smem writes visible. Pending groups at this point: NIT-1-it if
        // in the tail (no more stages), else 3. Leave at most min(pend-1, 2)
        // incomplete so group `it` is always drained.
        if (it + 3 <= NIT - 1)      { asm volatile("cp.async.wait_group 2;"); }
        else if (it == NIT - 2)     { asm volatile("cp.async.wait_group 1;"); }
        else if (it == NIT - 1)     { asm volatile("cp.async.wait_group 0;"); }
        else                        { asm volatile("cp.async.wait_group 2;"); }
        __syncthreads();
        // Stage buffer (it+3)%4 = (it-1)%4: legal, the barrier just proved all
        // threads finished compute on iteration it-1.
        if (it + 3 < NIT) stage(it + 3);

        const float* tbB = smem + (it & 3) * 2 * TILE_F;
        #pragma unroll
        for (int gg = 0; gg < 2; gg++) {
            const float* tb = tbB + gg * TILE_F;
            u64 aE0 = 0ull, aE1 = 0ull;       // packed chains (even taps)
            float sLo = 0.0f, sHi = 0.0f;     // scalar chains (odd taps)
            #pragma unroll
            for (int i = 0; i < KS; i++) {
                const u64* rp = (const u64*)(tb + (r + i) * PITCH + w0); // 8B al.
                u64 U0 = rp[0], U1 = rp[1], U2 = rp[2], U3 = rp[3];
                float f0, f1, f2, f3, f4, f5, f6, f7;
                unpack2(U0, f0, f1); unpack2(U1, f2, f3);
                unpack2(U2, f4, f5); unpack2(U3, f6, f7);
                u64& A = (i & 1) ? aE1 : aE0;
                ffma2(A, U0, Wr[i * 7 + 0]);
                ffma2(A, U1, Wr[i * 7 + 2]);
                ffma2(A, U2, Wr[i * 7 + 4]);
                ffma2(A, U3, Wr[i * 7 + 6]);
                odd_tap(sLo, sHi, f1, f2, Wr[i * 7 + 1]);
                odd_tap(sLo, sHi, f3, f4, Wr[i * 7 + 3]);
                odd_tap(sLo, sHi, f5, f6, Wr[i * 7 + 5]);
            }
            float p0, p1, q0, q1;
            unpack2(aE0, p0, p1);
            unpack2(aE1, q0, q1);
            *(u64*)op = pack2(p0 + q0 + sLo, p1 + q1 + sHi);
            op += CSTR;
        }
    }
}

extern "C" void kernel_launch(void* const* d_in, const int* in_sizes, int n_in,
                              void* d_out, int out_size) {
    const float* x = (const float*)d_in[0];
    const float* w = (const float*)d_in[1];
    // x (37,748,736 elems) > w (28,901,376); guard against input ordering.
    if (n_in >= 2 && in_sizes[0] < in_sizes[1]) {
        const float* t = x; x = w; w = t;
    }
    float* out = (float*)d_out;
    dim3 grid(H_ / HT, WC, N_);   // (48, 8, 8) = 3072 CTAs, 4 per SM
    ska_kernel<<<grid, NTHR>>>(x, w, out);
}